// round 3
// baseline (speedup 1.0000x reference)
#include <cuda_runtime.h>

#define N_TOTAL 65536
#define NNZ (16 * N_TOTAL)
#define STEPS 16

// Ping-pong state buffers (device globals: allocation-free scratch).
__device__ float g_Ur[2][N_TOTAL];
__device__ float g_Ui[2][N_TOTAL];

// ---------------------------------------------------------------------------
// Initialize buffer 0 from the harness inputs.
__global__ void init_kernel(const float* __restrict__ Ur0,
                            const float* __restrict__ Ui0) {
    int i = blockIdx.x * blockDim.x + threadIdx.x;
    if (i < N_TOTAL) {
        g_Ur[0][i] = Ur0[i];
        g_Ui[0][i] = Ui0[i];
    }
}

// ---------------------------------------------------------------------------
// dst = src (vectorized float4 copy of both Ur and Ui). 512 KB total.
__global__ void copy_kernel(int src) {
    int i = blockIdx.x * blockDim.x + threadIdx.x;   // over N_TOTAL/4
    int d = src ^ 1;
    const float4* sr = reinterpret_cast<const float4*>(g_Ur[src]);
    const float4* si = reinterpret_cast<const float4*>(g_Ui[src]);
    float4* dr = reinterpret_cast<float4*>(g_Ur[d]);
    float4* di = reinterpret_cast<float4*>(g_Ui[d]);
    if (i < N_TOTAL / 4) {
        dr[i] = sr[i];
        di[i] = si[i];
    }
}

// ---------------------------------------------------------------------------
// One fused scatter step: for each nnz,
//   Ur_new[r] -= dz*A*Ui_old[c];  Ui_new[r] += dz*A*Ur_old[c]
// Reads from src buffer only, writes (atomics) to dst buffer only -> no hazard.
__global__ __launch_bounds__(256)
void scatter_kernel(const float* __restrict__ A_vals,
                    const int* __restrict__ row_idx,
                    const int* __restrict__ col_idx,
                    float dz, int src) {
    int i = blockIdx.x * blockDim.x + threadIdx.x;
    if (i >= NNZ) return;
    int d = src ^ 1;
    float a = __ldg(&A_vals[i]) * dz;
    int r = __ldg(&row_idx[i]);
    int c = __ldg(&col_idx[i]);
    float ur = g_Ur[src][c];
    float ui = g_Ui[src][c];
    atomicAdd(&g_Ur[d][r], -a * ui);
    atomicAdd(&g_Ui[d][r],  a * ur);
}

// ---------------------------------------------------------------------------
// Write PLANAR output: out[0:N] = Ur (real), out[N:2N] = Ui (imag).
__global__ void out_kernel(float* __restrict__ out, int src) {
    int i = blockIdx.x * blockDim.x + threadIdx.x;
    if (i < N_TOTAL) {
        out[i]           = g_Ur[src][i];
        out[N_TOTAL + i] = g_Ui[src][i];
    }
}

// ---------------------------------------------------------------------------
extern "C" void kernel_launch(void* const* d_in, const int* in_sizes, int n_in,
                              void* d_out, int out_size) {
    const float* A_vals  = (const float*)d_in[0];
    const int*   row_idx = (const int*)d_in[1];
    const int*   col_idx = (const int*)d_in[2];
    const float* Ur0     = (const float*)d_in[3];
    const float* Ui0     = (const float*)d_in[4];
    // d_in[5] (Euler_steps) is a fixed scalar = 16; dz = 1/16 exactly.

    const float dz = 1.0f / (float)STEPS;

    const int TB = 256;
    init_kernel<<<(N_TOTAL + TB - 1) / TB, TB>>>(Ur0, Ui0);

    int src = 0;
    for (int s = 0; s < STEPS; s++) {
        copy_kernel<<<(N_TOTAL / 4 + TB - 1) / TB, TB>>>(src);
        scatter_kernel<<<(NNZ + TB - 1) / TB, TB>>>(A_vals, row_idx, col_idx,
                                                    dz, src);
        src ^= 1;
    }

    out_kernel<<<(N_TOTAL + TB - 1) / TB, TB>>>((float*)d_out, src);
}